// round 3
// baseline (speedup 1.0000x reference)
#include <cuda_runtime.h>
#include <cuda_bf16.h>

// DisplaceChannel: per-group bilinear shift.
// inp:    (B=16, C=256, H=128, W=128) fp32
// offset: (G=32, 2) fp32 ; dx = offset[g][0]*128, dy = offset[g][1]*128
// out[b,c,y,x] = w00*in[y+iy,x+ix]   + w01*in[y+iy,x+ix+1]
//              + w10*in[y+iy+1,x+ix] + w11*in[y+iy+1,x+ix+1]  (taps zero OOB)
//
// Layout: one warp = one full image row (32 lanes x 4 outputs = 128).
// All control state (iy, ix, r, row validity) is warp-uniform, and every
// LDG.128 has lanes at 16B stride -> fully dense 512B/instruction.

#define H 128
#define W 128
#define C 256

// 4 outputs from two 8-float window rows at compile-time shift R (0..3).
template<int R>
__device__ __forceinline__ void emit4(const float* __restrict__ ca,
                                      const float* __restrict__ cb,
                                      float w00, float w01, float w10, float w11,
                                      float4* __restrict__ outp)
{
    float o[4];
#pragma unroll
    for (int k = 0; k < 4; k++) {
        o[k] = w00 * ca[R + k] + w01 * ca[R + k + 1]
             + w10 * cb[R + k] + w11 * cb[R + k + 1];
    }
    *outp = make_float4(o[0], o[1], o[2], o[3]);
}

__global__ __launch_bounds__(256) void displace_kernel(
    const float* __restrict__ inp,
    const float* __restrict__ offset,
    float* __restrict__ out)
{
    // 4 outputs per thread.
    //   bits [0:5)  -> x-quad (lane)   : 32 quads of 4 = 128 x (one warp = one row)
    //   bits [5:12) -> y (128)         : block of 256 = 8 consecutive rows
    //   bits [12:)  -> plane = b*C + c (4096 planes)
    int t = blockIdx.x * blockDim.x + threadIdx.x;
    int x4    = (t & 31) << 2;       // 0,4,...,124
    int y     = (t >> 5) & 127;
    int plane = t >> 12;
    int c     = plane & (C - 1);
    int g     = c >> 3;

    // Per-group displacement (tiny L1-resident table).
    float dx = __ldg(offset + 2 * g)     * 128.0f;
    float dy = __ldg(offset + 2 * g + 1) * 128.0f;
    float x0f = floorf(dx);
    float y0f = floorf(dy);
    float fx = dx - x0f;
    float fy = dy - y0f;
    int ix = (int)x0f;
    int iy = (int)y0f;

    float w00 = (1.0f - fy) * (1.0f - fx);
    float w01 = (1.0f - fy) * fx;
    float w10 = fy * (1.0f - fx);
    float w11 = fy * fx;

    int r  = ix & 3;                 // warp-uniform misalignment (0..3)
    int a0 = x4 + ix - r;            // 4-aligned base of the 8-float window

    const float* base = inp + (size_t)plane * (H * W);
    int ys0 = y + iy;
    int ys1 = ys0 + 1;
    bool vy0 = ((unsigned)ys0) < (unsigned)H;   // warp-uniform
    bool vy1 = ((unsigned)ys1) < (unsigned)H;   // warp-uniform
    const float* row0 = base + ys0 * W;
    const float* row1 = base + ys1 * W;

    // Two aligned float4 chunks per tap-row. Chunks are 4-aligned and W%4==0,
    // so element validity == chunk validity.
    int p0 = a0;
    int p1 = a0 + 4;
    bool v0 = (p0 >= 0) && (p0 <= W - 4);
    bool v1 = (p1 >= 0) && (p1 <= W - 4);

    const float4 Z = make_float4(0.f, 0.f, 0.f, 0.f);
    float4 a_lo = (vy0 && v0) ? *(const float4*)(row0 + p0) : Z;
    float4 a_hi = (vy0 && v1) ? *(const float4*)(row0 + p1) : Z;
    float4 b_lo = (vy1 && v0) ? *(const float4*)(row1 + p0) : Z;
    float4 b_hi = (vy1 && v1) ? *(const float4*)(row1 + p1) : Z;

    float ca[8] = {a_lo.x, a_lo.y, a_lo.z, a_lo.w, a_hi.x, a_hi.y, a_hi.z, a_hi.w};
    float cb[8] = {b_lo.x, b_lo.y, b_lo.z, b_lo.w, b_hi.x, b_hi.y, b_hi.z, b_hi.w};

    float4* outp = (float4*)(out + (size_t)plane * (H * W) + y * W + x4);

    // r is warp-uniform -> uniform branch, no divergence.
    switch (r) {
        case 0: emit4<0>(ca, cb, w00, w01, w10, w11, outp); break;
        case 1: emit4<1>(ca, cb, w00, w01, w10, w11, outp); break;
        case 2: emit4<2>(ca, cb, w00, w01, w10, w11, outp); break;
        default: emit4<3>(ca, cb, w00, w01, w10, w11, outp); break;
    }
}

extern "C" void kernel_launch(void* const* d_in, const int* in_sizes, int n_in,
                              void* d_out, int out_size)
{
    const float* inp    = (const float*)d_in[0];
    const float* offset = (const float*)d_in[1];
    float* out = (float*)d_out;

    int threads = 256;
    int total = out_size / 4;                     // 16,777,216 threads
    int blocks = (total + threads - 1) / threads; // 65536
    displace_kernel<<<blocks, threads>>>(inp, offset, out);
}

// round 5
// speedup vs baseline: 1.1233x; 1.1233x over previous
#include <cuda_runtime.h>
#include <cuda_bf16.h>

// DisplaceChannel: per-group bilinear shift.
// inp:    (B=16, C=256, H=128, W=128) fp32
// offset: (G=32, 2) fp32 ; dx = offset[g][0]*128, dy = offset[g][1]*128
// out[b,c,y,x] = w00*in[y+iy,x+ix]   + w01*in[y+iy,x+ix+1]
//              + w10*in[y+iy+1,x+ix] + w11*in[y+iy+1,x+ix+1]  (taps zero OOB)
//
// Thread tile: 4x (x) x 4y outputs. Warp = full 128-wide row (lane*4),
// so every LDG.128/STG.128 is lane-dense (512B contiguous).
// 4 output rows reuse 5 tap rows held in registers (1.25 tap rows / out row).

#define H 128
#define W 128
#define C 256

template<int R>
__device__ __forceinline__ void emit_tile(const float rv[5][8],
                                          float w00, float w01, float w10, float w11,
                                          float* __restrict__ outbase)
{
#pragma unroll
    for (int k = 0; k < 4; k++) {
        float o[4];
#pragma unroll
        for (int i = 0; i < 4; i++) {
            o[i] = w00 * rv[k][R + i]     + w01 * rv[k][R + i + 1]
                 + w10 * rv[k + 1][R + i] + w11 * rv[k + 1][R + i + 1];
        }
        *(float4*)(outbase + k * W) = make_float4(o[0], o[1], o[2], o[3]);
    }
}

__global__ __launch_bounds__(256) void displace_kernel(
    const float* __restrict__ inp,
    const float* __restrict__ offset,
    float* __restrict__ out)
{
    // Block: 8 warps; each warp covers x=0..127 for 4 consecutive rows.
    // Block covers 32 rows of one plane. Grid = 4096 planes * 4 ytiles.
    int lane = threadIdx.x & 31;
    int warp = threadIdx.x >> 5;
    int blk  = blockIdx.x;
    int plane = blk >> 2;                  // 0..4095
    int y0    = ((blk & 3) << 5) + (warp << 2);  // base output row (multiple of 4)
    int x4    = lane << 2;                 // 0,4,...,124

    int c = plane & (C - 1);
    int g = c >> 3;

    float dx = __ldg(offset + 2 * g)     * 128.0f;
    float dy = __ldg(offset + 2 * g + 1) * 128.0f;
    float x0f = floorf(dx);
    float y0f = floorf(dy);
    float fx = dx - x0f;
    float fy = dy - y0f;
    int ix = (int)x0f;
    int iy = (int)y0f;

    float w00 = (1.0f - fy) * (1.0f - fx);
    float w01 = (1.0f - fy) * fx;
    float w10 = fy * (1.0f - fx);
    float w11 = fy * fx;

    int r  = ix & 3;          // warp-uniform misalignment
    int a0 = x4 + ix - r;     // 4-aligned base of the 8-float x-window

    // Chunk validity (4-aligned chunks, W % 4 == 0 -> element validity == chunk validity)
    int p0 = a0;
    int p1 = a0 + 4;
    bool v0 = (p0 >= 0) && (p0 <= W - 4);
    bool v1 = (p1 >= 0) && (p1 <= W - 4);

    const float* base = inp + (size_t)plane * (H * W);
    const float4 Z = make_float4(0.f, 0.f, 0.f, 0.f);

    // Load 5 tap rows (ys = y0+iy+j, j=0..4), 2 dense float4 chunks each.
    float rv[5][8];
#pragma unroll
    for (int j = 0; j < 5; j++) {
        int ys = y0 + iy + j;
        bool vy = ((unsigned)ys) < (unsigned)H;   // warp-uniform
        const float* row = base + ys * W;
        float4 lo = (vy && v0) ? *(const float4*)(row + p0) : Z;
        float4 hi = (vy && v1) ? *(const float4*)(row + p1) : Z;
        rv[j][0] = lo.x; rv[j][1] = lo.y; rv[j][2] = lo.z; rv[j][3] = lo.w;
        rv[j][4] = hi.x; rv[j][5] = hi.y; rv[j][6] = hi.z; rv[j][7] = hi.w;
    }

    float* outbase = out + (size_t)plane * (H * W) + y0 * W + x4;

    // r is warp-uniform -> uniform branch.
    switch (r) {
        case 0: emit_tile<0>(rv, w00, w01, w10, w11, outbase); break;
        case 1: emit_tile<1>(rv, w00, w01, w10, w11, outbase); break;
        case 2: emit_tile<2>(rv, w00, w01, w10, w11, outbase); break;
        default: emit_tile<3>(rv, w00, w01, w10, w11, outbase); break;
    }
}

extern "C" void kernel_launch(void* const* d_in, const int* in_sizes, int n_in,
                              void* d_out, int out_size)
{
    const float* inp    = (const float*)d_in[0];
    const float* offset = (const float*)d_in[1];
    float* out = (float*)d_out;

    // 4096 planes * 4 ytiles = 16384 blocks of 256 threads.
    int blocks = 16384;
    displace_kernel<<<blocks, 256>>>(inp, offset, out);
}

// round 6
// speedup vs baseline: 1.1255x; 1.0020x over previous
#include <cuda_runtime.h>
#include <cuda_bf16.h>

// DisplaceChannel: per-group bilinear shift.
// inp:    (B=16, C=256, H=128, W=128) fp32
// offset: (G=32, 2) fp32 ; dx = offset[g][0]*128, dy = offset[g][1]*128
// out[b,c,y,x] = w00*in[y+iy,x+ix]   + w01*in[y+iy,x+ix+1]
//              + w10*in[y+iy+1,x+ix] + w11*in[y+iy+1,x+ix+1]  (taps zero OOB)
//
// Thread tile: 4x (x) x 4y outputs. Warp = full 128-wide row (lane*4),
// so every LDG.128/STG.128 is lane-dense (512B contiguous).
// 4 output rows reuse 5 tap rows held in registers.
// R6 change: stores use st.global.cs (evict-first) — output is write-once,
// never re-read; keep L2 capacity for input tap-row reuse.

#define H 128
#define W 128
#define C 256

__device__ __forceinline__ void stg_cs_v4(float* p, float4 v)
{
    asm volatile("st.global.cs.v4.f32 [%0], {%1, %2, %3, %4};"
                 :: "l"(p), "f"(v.x), "f"(v.y), "f"(v.z), "f"(v.w)
                 : "memory");
}

template<int R>
__device__ __forceinline__ void emit_tile(const float rv[5][8],
                                          float w00, float w01, float w10, float w11,
                                          float* __restrict__ outbase)
{
#pragma unroll
    for (int k = 0; k < 4; k++) {
        float o[4];
#pragma unroll
        for (int i = 0; i < 4; i++) {
            o[i] = w00 * rv[k][R + i]     + w01 * rv[k][R + i + 1]
                 + w10 * rv[k + 1][R + i] + w11 * rv[k + 1][R + i + 1];
        }
        stg_cs_v4(outbase + k * W, make_float4(o[0], o[1], o[2], o[3]));
    }
}

__global__ __launch_bounds__(256) void displace_kernel(
    const float* __restrict__ inp,
    const float* __restrict__ offset,
    float* __restrict__ out)
{
    // Block: 8 warps; each warp covers x=0..127 for 4 consecutive rows.
    // Block covers 32 rows of one plane. Grid = 4096 planes * 4 ytiles.
    int lane = threadIdx.x & 31;
    int warp = threadIdx.x >> 5;
    int blk  = blockIdx.x;
    int plane = blk >> 2;                        // 0..4095
    int y0    = ((blk & 3) << 5) + (warp << 2);  // base output row (multiple of 4)
    int x4    = lane << 2;                       // 0,4,...,124

    int c = plane & (C - 1);
    int g = c >> 3;

    float dx = __ldg(offset + 2 * g)     * 128.0f;
    float dy = __ldg(offset + 2 * g + 1) * 128.0f;
    float x0f = floorf(dx);
    float y0f = floorf(dy);
    float fx = dx - x0f;
    float fy = dy - y0f;
    int ix = (int)x0f;
    int iy = (int)y0f;

    float w00 = (1.0f - fy) * (1.0f - fx);
    float w01 = (1.0f - fy) * fx;
    float w10 = fy * (1.0f - fx);
    float w11 = fy * fx;

    int r  = ix & 3;          // warp-uniform misalignment
    int a0 = x4 + ix - r;     // 4-aligned base of the 8-float x-window

    // Chunk validity (4-aligned chunks, W % 4 == 0 -> element validity == chunk validity)
    int p0 = a0;
    int p1 = a0 + 4;
    bool v0 = (p0 >= 0) && (p0 <= W - 4);
    bool v1 = (p1 >= 0) && (p1 <= W - 4);

    const float* base = inp + (size_t)plane * (H * W);
    const float4 Z = make_float4(0.f, 0.f, 0.f, 0.f);

    // Load 5 tap rows (ys = y0+iy+j, j=0..4), 2 dense float4 chunks each.
    float rv[5][8];
#pragma unroll
    for (int j = 0; j < 5; j++) {
        int ys = y0 + iy + j;
        bool vy = ((unsigned)ys) < (unsigned)H;   // warp-uniform
        const float* row = base + ys * W;
        float4 lo = (vy && v0) ? *(const float4*)(row + p0) : Z;
        float4 hi = (vy && v1) ? *(const float4*)(row + p1) : Z;
        rv[j][0] = lo.x; rv[j][1] = lo.y; rv[j][2] = lo.z; rv[j][3] = lo.w;
        rv[j][4] = hi.x; rv[j][5] = hi.y; rv[j][6] = hi.z; rv[j][7] = hi.w;
    }

    float* outbase = out + (size_t)plane * (H * W) + y0 * W + x4;

    // r is warp-uniform -> uniform branch.
    switch (r) {
        case 0: emit_tile<0>(rv, w00, w01, w10, w11, outbase); break;
        case 1: emit_tile<1>(rv, w00, w01, w10, w11, outbase); break;
        case 2: emit_tile<2>(rv, w00, w01, w10, w11, outbase); break;
        default: emit_tile<3>(rv, w00, w01, w10, w11, outbase); break;
    }
}

extern "C" void kernel_launch(void* const* d_in, const int* in_sizes, int n_in,
                              void* d_out, int out_size)
{
    const float* inp    = (const float*)d_in[0];
    const float* offset = (const float*)d_in[1];
    float* out = (float*)d_out;

    // 4096 planes * 4 ytiles = 16384 blocks of 256 threads.
    displace_kernel<<<16384, 256>>>(inp, offset, out);
}